// round 6
// baseline (speedup 1.0000x reference)
#include <cuda_runtime.h>

// Problem constants (fixed by setup_inputs): assignments [512, 8192] int32,
// vocab = 50257, output [512, 50257] float32.
#define VOCAB   50257
#define SEQ     8192
#define THREADS 1024

// One CTA per batch row. Full-vocab histogram lives in dynamic shared memory
// (50257 * 4 B = 196.3 KB < 227 KB cap -> 1 CTA/SM).
__global__ __launch_bounds__(THREADS, 1)
void XTermFrequency_hist_kernel(const int* __restrict__ assign,
                                float* __restrict__ out) {
    extern __shared__ unsigned int s_hist[];

    const int b   = blockIdx.x;
    const int tid = threadIdx.x;

    // 1) Zero the shared histogram (ceil(50257/1024) = 50 iters/thread).
    for (int i = tid; i < VOCAB; i += THREADS) {
        s_hist[i] = 0u;
    }
    __syncthreads();

    // 2) Histogram the row. SEQ/4 = 2048 int4 loads, 2 per thread (LDG.128).
    //    Indices are ~uniform over 50257 bins -> smem atomics mostly
    //    conflict-free.
    const int4* __restrict__ row =
        reinterpret_cast<const int4*>(assign + (size_t)b * SEQ);
    #pragma unroll
    for (int i = tid; i < SEQ / 4; i += THREADS) {
        const int4 v = row[i];
        atomicAdd(&s_hist[v.x], 1u);
        atomicAdd(&s_hist[v.y], 1u);
        atomicAdd(&s_hist[v.z], 1u);
        atomicAdd(&s_hist[v.w], 1u);
    }
    __syncthreads();

    // 3) Convert counts -> frequency and stream out (coalesced STG.32).
    //    Row sums are exactly SEQ, so frequency = count * (1/SEQ), exact in
    //    fp32 since 1/8192 is a power of two and counts <= 8192.
    float* __restrict__ orow = out + (size_t)b * VOCAB;
    const float inv = 1.0f / (float)SEQ;
    for (int i = tid; i < VOCAB; i += THREADS) {
        orow[i] = (float)s_hist[i] * inv;
    }
}

extern "C" void kernel_launch(void* const* d_in, const int* in_sizes, int n_in,
                              void* d_out, int out_size) {
    const int* assign = (const int*)d_in[0];   // [batch, SEQ] int32
    float*     out    = (float*)d_out;         // [batch, VOCAB] float32

    const int batch = in_sizes[0] / SEQ;       // 512
    const size_t smem_bytes = (size_t)VOCAB * sizeof(unsigned int);  // 196.3 KB

    // Opt in to >48 KB dynamic smem. Host-side attribute set, not a stream
    // op -> graph-capture safe; called unconditionally (deterministic).
    cudaFuncSetAttribute(XTermFrequency_hist_kernel,
                         cudaFuncAttributeMaxDynamicSharedMemorySize,
                         (int)smem_bytes);

    XTermFrequency_hist_kernel<<<batch, THREADS, smem_bytes>>>(assign, out);
}